// round 1
// baseline (speedup 1.0000x reference)
#include <cuda_runtime.h>
#include <cstddef>

#define B_   8
#define C_   256
#define N_   1024      // 32*32 spatial flattened
#define EXP_ 4
#define NN_  (N_*N_)

// ---------------- scratch (static device arrays; no runtime alloc) -----------
__device__ float g_dwq[B_*C_*N_];
__device__ float g_dwk[B_*C_*N_];
__device__ float g_dwv[B_*C_*N_];
__device__ float g_q  [B_*C_*N_];
__device__ float g_k  [B_*EXP_*C_*N_];
__device__ float g_v  [B_*C_*N_];
__device__ float g_attn [B_*EXP_*NN_];   // pre-gate attention (post qk*scale)
__device__ float g_gated[B_*EXP_*NN_];   // attn * softmax(attn)
__device__ float g_out0[B_*C_*N_];       // attn @ v^T before proj conv

// ---------------- K1: fused 3-branch depthwise 3x3 + bias --------------------
__global__ void dw3_kernel(const float* __restrict__ x,
                           const float* __restrict__ wq, const float* __restrict__ bq,
                           const float* __restrict__ wk, const float* __restrict__ bk,
                           const float* __restrict__ wv, const float* __restrict__ bv)
{
    __shared__ float plane[N_];
    int bc = blockIdx.x; int b = bc >> 8, c = bc & 255;
    const float* src = x + ((size_t)(b*C_ + c))*N_;
    int tid = threadIdx.x;
    for (int i = tid; i < N_; i += 256) plane[i] = src[i];
    __syncthreads();
    float wwq[9], wwk[9], wwv[9];
    #pragma unroll
    for (int t = 0; t < 9; t++) { wwq[t]=wq[c*9+t]; wwk[t]=wk[c*9+t]; wwv[t]=wv[c*9+t]; }
    float bbq = bq[c], bbk = bk[c], bbv = bv[c];
    for (int i = tid; i < N_; i += 256) {
        int h = i >> 5, w = i & 31;
        float aq = bbq, ak = bbk, av = bbv;
        #pragma unroll
        for (int ky = 0; ky < 3; ky++) {
            int hh = h + ky - 1; if ((unsigned)hh >= 32u) continue;
            #pragma unroll
            for (int kx = 0; kx < 3; kx++) {
                int ww = w + kx - 1; if ((unsigned)ww >= 32u) continue;
                float in = plane[hh*32 + ww];
                aq += wwq[ky*3+kx]*in; ak += wwk[ky*3+kx]*in; av += wwv[ky*3+kx]*in;
            }
        }
        size_t o = ((size_t)(b*C_ + c))*N_ + i;
        g_dwq[o] = aq; g_dwk[o] = ak; g_dwv[o] = av;
    }
}

// ---------------- K2: pointwise conv = SGEMM  Y[b,oc,n] = W[oc,:]·T[b,:,n]+bias
// W row-major [OC, 256] (transpose-load), T [256, 1024] per batch (direct).
__global__ void pw_gemm(const float* __restrict__ W, const float* __restrict__ bias,
                        const float* __restrict__ T, float* __restrict__ Y, int OC)
{
    __shared__ float As[16][68];
    __shared__ float Bs[16][68];
    int b = blockIdx.z;
    int mBase = blockIdx.y * 64, nBase = blockIdx.x * 64;
    int tid = threadIdx.x, tx = tid & 15, ty = tid >> 4;
    const float* Ag = W + (size_t)mBase * C_;
    const float* Bg = T + (size_t)b * C_ * N_ + nBase;
    float acc[4][4] = {};
    int ra = tid >> 2, ca = (tid & 3) << 2;
    int rb = tid >> 4, cb = (tid & 15) << 2;
    for (int k0 = 0; k0 < C_; k0 += 16) {
        float4 a = *(const float4*)&Ag[(size_t)ra*C_ + k0 + ca];
        As[ca+0][ra]=a.x; As[ca+1][ra]=a.y; As[ca+2][ra]=a.z; As[ca+3][ra]=a.w;
        *(float4*)&Bs[rb][cb] = *(const float4*)&Bg[(size_t)(k0+rb)*N_ + cb];
        __syncthreads();
        #pragma unroll
        for (int kk = 0; kk < 16; kk++) {
            float4 a4 = *(float4*)&As[kk][ty<<2];
            float4 b4 = *(float4*)&Bs[kk][tx<<2];
            float ar[4]={a4.x,a4.y,a4.z,a4.w}, br[4]={b4.x,b4.y,b4.z,b4.w};
            #pragma unroll
            for (int i=0;i<4;i++)
                #pragma unroll
                for (int j=0;j<4;j++) acc[i][j] += ar[i]*br[j];
        }
        __syncthreads();
    }
    #pragma unroll
    for (int i = 0; i < 4; i++) {
        int m = mBase + (ty<<2) + i;
        float bi = bias[m];
        float4 o = make_float4(acc[i][0]+bi, acc[i][1]+bi, acc[i][2]+bi, acc[i][3]+bi);
        *(float4*)&Y[((size_t)b*OC + m)*N_ + nBase + (tx<<2)] = o;
    }
}

// ---------------- K3: attn[b,e,n,m] = scale * sum_c q[b,c,n]*k[b,e*C+c,m] ----
__global__ void qk_gemm()
{
    __shared__ float As[16][68];
    __shared__ float Bs[16][68];
    int z = blockIdx.z;                       // b*4+e
    int b = z >> 2;
    int nBase = blockIdx.y * 64;              // output row (n)
    int mBase = blockIdx.x * 64;              // output col (m)
    const float* Ag = g_q + (size_t)b*C_*N_ + nBase;      // [c][n]
    const float* Bg = g_k + (size_t)z*C_*N_ + mBase;      // [c][m]  (z*C = (b*4+e)*C)
    int tid = threadIdx.x, tx = tid & 15, ty = tid >> 4;
    int rb = tid >> 4, cb = (tid & 15) << 2;
    float acc[4][4] = {};
    for (int k0 = 0; k0 < C_; k0 += 16) {
        *(float4*)&As[rb][cb] = *(const float4*)&Ag[(size_t)(k0+rb)*N_ + cb];
        *(float4*)&Bs[rb][cb] = *(const float4*)&Bg[(size_t)(k0+rb)*N_ + cb];
        __syncthreads();
        #pragma unroll
        for (int kk = 0; kk < 16; kk++) {
            float4 a4 = *(float4*)&As[kk][ty<<2];
            float4 b4 = *(float4*)&Bs[kk][tx<<2];
            float ar[4]={a4.x,a4.y,a4.z,a4.w}, br[4]={b4.x,b4.y,b4.z,b4.w};
            #pragma unroll
            for (int i=0;i<4;i++)
                #pragma unroll
                for (int j=0;j<4;j++) acc[i][j] += ar[i]*br[j];
        }
        __syncthreads();
    }
    const float scale = 0.0625f;   // 256^-0.5
    #pragma unroll
    for (int i = 0; i < 4; i++) {
        int n = nBase + (ty<<2) + i;
        float4 o = make_float4(acc[i][0]*scale, acc[i][1]*scale, acc[i][2]*scale, acc[i][3]*scale);
        *(float4*)&g_attn[((size_t)z*N_ + n)*N_ + mBase + (tx<<2)] = o;
    }
}

// ------- K4: fused 3x3 conv(4->4) + BN + self-gated softmax over last dim ----
// one block = one output row n of one batch b (all 4 channels, all 1024 m)
__global__ void conv0_gate_kernel(const float* __restrict__ w0,
                                  const float* __restrict__ gma, const float* __restrict__ bta,
                                  const float* __restrict__ mu,  const float* __restrict__ var)
{
    __shared__ float rows[3][N_];
    __shared__ float wsm[144];
    __shared__ float red[256];
    int n = blockIdx.x, b = blockIdx.y, tid = threadIdx.x;
    if (tid < 144) wsm[tid] = w0[tid];
    float sc[4], sh[4];
    #pragma unroll
    for (int f = 0; f < 4; f++) {
        float inv = rsqrtf(var[f] + 1e-5f);
        sc[f] = gma[f] * inv; sh[f] = bta[f] - mu[f] * sc[f];
    }
    float acc[4][4] = {};
    for (int e = 0; e < 4; e++) {
        __syncthreads();
        #pragma unroll
        for (int r = 0; r < 3; r++) {
            int nn = n + r - 1;
            bool ok = (unsigned)nn < (unsigned)N_;
            const float* src = g_attn + (((size_t)(b*4 + e))*N_ + (ok ? nn : 0))*N_;
            for (int i = tid; i < N_; i += 256) rows[r][i] = ok ? src[i] : 0.f;
        }
        __syncthreads();
        #pragma unroll
        for (int t = 0; t < 9; t++) {
            int ky = t / 3, kx = t % 3;
            float w0r = wsm[(0*4+e)*9+t], w1r = wsm[(1*4+e)*9+t];
            float w2r = wsm[(2*4+e)*9+t], w3r = wsm[(3*4+e)*9+t];
            #pragma unroll
            for (int j = 0; j < 4; j++) {
                int m = tid + 256*j + kx - 1;
                float in = ((unsigned)m < (unsigned)N_) ? rows[ky][m] : 0.f;
                acc[0][j] += w0r*in; acc[1][j] += w1r*in;
                acc[2][j] += w2r*in; acc[3][j] += w3r*in;
            }
        }
    }
    #pragma unroll
    for (int f = 0; f < 4; f++)
        #pragma unroll
        for (int j = 0; j < 4; j++) acc[f][j] = acc[f][j]*sc[f] + sh[f];

    // per-channel softmax over the 1024 m positions, then gated write
    for (int f = 0; f < 4; f++) {
        float mx4 = fmaxf(fmaxf(acc[f][0], acc[f][1]), fmaxf(acc[f][2], acc[f][3]));
        __syncthreads();
        red[tid] = mx4; __syncthreads();
        for (int s = 128; s > 0; s >>= 1) { if (tid < s) red[tid] = fmaxf(red[tid], red[tid+s]); __syncthreads(); }
        float mx = red[0];
        float es[4]; float psum = 0.f;
        #pragma unroll
        for (int j = 0; j < 4; j++) { es[j] = expf(acc[f][j] - mx); psum += es[j]; }
        __syncthreads();
        red[tid] = psum; __syncthreads();
        for (int s = 128; s > 0; s >>= 1) { if (tid < s) red[tid] += red[tid+s]; __syncthreads(); }
        float inv = 1.f / red[0];
        float* dst = g_gated + (((size_t)(b*4 + f))*N_ + n)*N_;
        #pragma unroll
        for (int j = 0; j < 4; j++) dst[tid + 256*j] = acc[f][j] * es[j] * inv;
    }
}

// ---------------- K5: 3x3 conv(4->1) on gated -> final attn (second output) --
__global__ void attn1_kernel(const float* __restrict__ w1, float* __restrict__ dst)
{
    __shared__ float rows[3][N_];
    int n = blockIdx.x, b = blockIdx.y, tid = threadIdx.x;
    float acc[4] = {};
    for (int e = 0; e < 4; e++) {
        __syncthreads();
        #pragma unroll
        for (int r = 0; r < 3; r++) {
            int nn = n + r - 1;
            bool ok = (unsigned)nn < (unsigned)N_;
            const float* src = g_gated + (((size_t)(b*4 + e))*N_ + (ok ? nn : 0))*N_;
            for (int i = tid; i < N_; i += 256) rows[r][i] = ok ? src[i] : 0.f;
        }
        __syncthreads();
        #pragma unroll
        for (int t = 0; t < 9; t++) {
            float wv = w1[e*9 + t];
            int ky = t / 3, kx = t % 3;
            #pragma unroll
            for (int j = 0; j < 4; j++) {
                int m = tid + 256*j + kx - 1;
                float in = ((unsigned)m < (unsigned)N_) ? rows[ky][m] : 0.f;
                acc[j] += wv * in;
            }
        }
    }
    #pragma unroll
    for (int j = 0; j < 4; j++)
        dst[((size_t)b*N_ + n)*N_ + tid + 256*j] = acc[j];
}

// ---------------- K6: out0[b,c,n] = sum_m v[b,c,m]*attnF[b,n,m]  (NT GEMM) ---
__global__ void av_gemm(const float* __restrict__ attnF)
{
    __shared__ float As[16][68];
    __shared__ float Bs[16][68];
    int b = blockIdx.z;
    int mBase = blockIdx.y * 64;   // c
    int nBase = blockIdx.x * 64;   // n
    const float* Ag = g_v  + ((size_t)b*C_ + mBase)*N_;   // [c][m], K-minor
    const float* Bg = attnF + (size_t)b*NN_ + (size_t)nBase*N_; // [n][m], K-minor
    int tid = threadIdx.x, tx = tid & 15, ty = tid >> 4;
    int r = tid >> 2, c4 = (tid & 3) << 2;
    float acc[4][4] = {};
    for (int k0 = 0; k0 < N_; k0 += 16) {
        float4 a = *(const float4*)&Ag[(size_t)r*N_ + k0 + c4];
        As[c4+0][r]=a.x; As[c4+1][r]=a.y; As[c4+2][r]=a.z; As[c4+3][r]=a.w;
        float4 bq = *(const float4*)&Bg[(size_t)r*N_ + k0 + c4];
        Bs[c4+0][r]=bq.x; Bs[c4+1][r]=bq.y; Bs[c4+2][r]=bq.z; Bs[c4+3][r]=bq.w;
        __syncthreads();
        #pragma unroll
        for (int kk = 0; kk < 16; kk++) {
            float4 a4 = *(float4*)&As[kk][ty<<2];
            float4 b4 = *(float4*)&Bs[kk][tx<<2];
            float ar[4]={a4.x,a4.y,a4.z,a4.w}, br[4]={b4.x,b4.y,b4.z,b4.w};
            #pragma unroll
            for (int i=0;i<4;i++)
                #pragma unroll
                for (int j=0;j<4;j++) acc[i][j] += ar[i]*br[j];
        }
        __syncthreads();
    }
    #pragma unroll
    for (int i = 0; i < 4; i++) {
        int c = mBase + (ty<<2) + i;
        float4 o = make_float4(acc[i][0], acc[i][1], acc[i][2], acc[i][3]);
        *(float4*)&g_out0[((size_t)b*C_ + c)*N_ + nBase + (tx<<2)] = o;
    }
}

// ---------------- K7: proj 3x3 conv (256->256, no bias) -> first output ------
__global__ void proj_kernel(const float* __restrict__ pw, float* __restrict__ dst)
{
    __shared__ float inT[8][34*34];
    __shared__ float wT[4][8][9];
    int ocg = blockIdx.x;          // 0..63 (4 oc each)
    int b   = blockIdx.y;
    int tid = threadIdx.x;
    int base34[4];
    #pragma unroll
    for (int i = 0; i < 4; i++) {
        int sp = tid + 256*i; int h = sp >> 5, w = sp & 31;
        base34[i] = h*34 + w;      // tile index of (h-1,w-1) shifted by halo
    }
    float acc[4][4] = {};
    for (int cc = 0; cc < 32; cc++) {
        __syncthreads();
        for (int idx = tid; idx < 8*1156; idx += 256) {
            int ic = idx / 1156, rem = idx % 1156;
            int hh = rem / 34 - 1, ww = rem % 34 - 1;
            float v = 0.f;
            if ((unsigned)hh < 32u && (unsigned)ww < 32u)
                v = g_out0[((size_t)b*C_ + cc*8 + ic)*N_ + hh*32 + ww];
            inT[ic][rem] = v;
        }
        for (int idx = tid; idx < 288; idx += 256) {
            int oc = idx / 72, r2 = idx % 72, ic = r2 / 9, t = r2 % 9;
            wT[oc][ic][t] = pw[((size_t)(ocg*4 + oc)*C_ + cc*8 + ic)*9 + t];
        }
        __syncthreads();
        #pragma unroll
        for (int ic = 0; ic < 8; ic++) {
            #pragma unroll
            for (int t = 0; t < 9; t++) {
                int off = (t/3)*34 + (t%3);
                float w0 = wT[0][ic][t], w1 = wT[1][ic][t];
                float w2 = wT[2][ic][t], w3 = wT[3][ic][t];
                #pragma unroll
                for (int i = 0; i < 4; i++) {
                    float in = inT[ic][base34[i] + off];
                    acc[0][i] += w0*in; acc[1][i] += w1*in;
                    acc[2][i] += w2*in; acc[3][i] += w3*in;
                }
            }
        }
    }
    #pragma unroll
    for (int oc = 0; oc < 4; oc++)
        #pragma unroll
        for (int i = 0; i < 4; i++)
            dst[((size_t)b*C_ + ocg*4 + oc)*N_ + tid + 256*i] = acc[oc][i];
}

// ---------------------------------------------------------------------------
extern "C" void kernel_launch(void* const* d_in, const int* in_sizes, int n_in,
                              void* d_out, int out_size)
{
    const float* x       = (const float*)d_in[0];
    const float* qa_dw_w = (const float*)d_in[1];
    const float* qa_dw_b = (const float*)d_in[2];
    const float* qa_pw_w = (const float*)d_in[3];
    const float* qa_pw_b = (const float*)d_in[4];
    const float* ka_dw_w = (const float*)d_in[5];
    const float* ka_dw_b = (const float*)d_in[6];
    const float* ka_pw_w = (const float*)d_in[7];
    const float* ka_pw_b = (const float*)d_in[8];
    const float* va_dw_w = (const float*)d_in[9];
    const float* va_dw_b = (const float*)d_in[10];
    const float* va_pw_w = (const float*)d_in[11];
    const float* va_pw_b = (const float*)d_in[12];
    const float* attn0_w = (const float*)d_in[13];
    const float* bn_g    = (const float*)d_in[14];
    const float* bn_b    = (const float*)d_in[15];
    const float* bn_m    = (const float*)d_in[16];
    const float* bn_v    = (const float*)d_in[17];
    const float* attn1_w = (const float*)d_in[18];
    const float* proj_w  = (const float*)d_in[19];

    float* out_main = (float*)d_out;                 // [8,256,32,32]
    float* out_attn = out_main + (size_t)B_*C_*N_;   // [8,1,1024,1024]

    void *p_dwq, *p_dwk, *p_dwv, *p_q, *p_k, *p_v;
    cudaGetSymbolAddress(&p_dwq, g_dwq);
    cudaGetSymbolAddress(&p_dwk, g_dwk);
    cudaGetSymbolAddress(&p_dwv, g_dwv);
    cudaGetSymbolAddress(&p_q,   g_q);
    cudaGetSymbolAddress(&p_k,   g_k);
    cudaGetSymbolAddress(&p_v,   g_v);

    // K1: fused depthwise for q/k/v branches
    dw3_kernel<<<B_*C_, 256>>>(x, qa_dw_w, qa_dw_b, ka_dw_w, ka_dw_b, va_dw_w, va_dw_b);

    // K2: pointwise GEMMs (+bias)
    pw_gemm<<<dim3(16, 4, B_), 256>>>(qa_pw_w, qa_pw_b, (const float*)p_dwq, (float*)p_q, 256);
    pw_gemm<<<dim3(16,16, B_), 256>>>(ka_pw_w, ka_pw_b, (const float*)p_dwk, (float*)p_k, 1024);
    pw_gemm<<<dim3(16, 4, B_), 256>>>(va_pw_w, va_pw_b, (const float*)p_dwv, (float*)p_v, 256);

    // K3: q^T k  -> attn [B,4,N,N], scaled
    qk_gemm<<<dim3(16, 16, B_*EXP_), 256>>>();

    // K4: conv0 + BN + self-gated softmax (fused, row-wise)
    conv0_gate_kernel<<<dim3(N_, B_), 256>>>(attn0_w, bn_g, bn_b, bn_m, bn_v);

    // K5: conv attn1 (4->1) -> second output
    attn1_kernel<<<dim3(N_, B_), 256>>>(attn1_w, out_attn);

    // K6: attn @ v^T -> out0
    av_gemm<<<dim3(16, 4, B_), 256>>>(out_attn);

    // K7: proj 3x3 conv -> first output
    proj_kernel<<<dim3(64, B_), 256>>>(proj_w, out_main);
}

// round 2
// speedup vs baseline: 1.0002x; 1.0002x over previous
#include <cuda_runtime.h>
#include <cstddef>

#define B_   8
#define C_   256
#define N_   1024      // 32*32 spatial flattened
#define EXP_ 4
#define NN_  (N_*N_)

// ---------------- scratch (static device arrays; no runtime alloc) -----------
__device__ float g_dwq[B_*C_*N_];
__device__ float g_dwk[B_*C_*N_];
__device__ float g_dwv[B_*C_*N_];
__device__ float g_q  [B_*C_*N_];
__device__ float g_k  [B_*EXP_*C_*N_];
__device__ float g_v  [B_*C_*N_];
__device__ float g_attn [B_*EXP_*NN_];   // pre-gate attention (post qk*scale)
__device__ float g_gated[B_*EXP_*NN_];   // attn * softmax(attn)
__device__ float g_out0[B_*C_*N_];       // attn @ v^T before proj conv

// ---------------- K1: fused 3-branch depthwise 3x3 + bias --------------------
__global__ void dw3_kernel(const float* __restrict__ x,
                           const float* __restrict__ wq, const float* __restrict__ bq,
                           const float* __restrict__ wk, const float* __restrict__ bk,
                           const float* __restrict__ wv, const float* __restrict__ bv)
{
    __shared__ float plane[N_];
    int bc = blockIdx.x; int b = bc >> 8, c = bc & 255;
    const float* src = x + ((size_t)(b*C_ + c))*N_;
    int tid = threadIdx.x;
    for (int i = tid; i < N_; i += 256) plane[i] = src[i];
    __syncthreads();
    float wwq[9], wwk[9], wwv[9];
    #pragma unroll
    for (int t = 0; t < 9; t++) { wwq[t]=wq[c*9+t]; wwk[t]=wk[c*9+t]; wwv[t]=wv[c*9+t]; }
    float bbq = bq[c], bbk = bk[c], bbv = bv[c];
    for (int i = tid; i < N_; i += 256) {
        int h = i >> 5, w = i & 31;
        float aq = bbq, ak = bbk, av = bbv;
        #pragma unroll
        for (int ky = 0; ky < 3; ky++) {
            int hh = h + ky - 1; if ((unsigned)hh >= 32u) continue;
            #pragma unroll
            for (int kx = 0; kx < 3; kx++) {
                int ww = w + kx - 1; if ((unsigned)ww >= 32u) continue;
                float in = plane[hh*32 + ww];
                aq += wwq[ky*3+kx]*in; ak += wwk[ky*3+kx]*in; av += wwv[ky*3+kx]*in;
            }
        }
        size_t o = ((size_t)(b*C_ + c))*N_ + i;
        g_dwq[o] = aq; g_dwk[o] = ak; g_dwv[o] = av;
    }
}

// ---------------- K2: pointwise conv = SGEMM  Y[b,oc,n] = W[oc,:]·T[b,:,n]+bias
// W row-major [OC, 256] (transpose-load), T [256, 1024] per batch (direct).
__global__ void pw_gemm(const float* __restrict__ W, const float* __restrict__ bias,
                        const float* __restrict__ T, float* __restrict__ Y, int OC)
{
    __shared__ float As[16][68];
    __shared__ float Bs[16][68];
    int b = blockIdx.z;
    int mBase = blockIdx.y * 64, nBase = blockIdx.x * 64;
    int tid = threadIdx.x, tx = tid & 15, ty = tid >> 4;
    const float* Ag = W + (size_t)mBase * C_;
    const float* Bg = T + (size_t)b * C_ * N_ + nBase;
    float acc[4][4] = {};
    int ra = tid >> 2, ca = (tid & 3) << 2;
    int rb = tid >> 4, cb = (tid & 15) << 2;
    for (int k0 = 0; k0 < C_; k0 += 16) {
        float4 a = *(const float4*)&Ag[(size_t)ra*C_ + k0 + ca];
        As[ca+0][ra]=a.x; As[ca+1][ra]=a.y; As[ca+2][ra]=a.z; As[ca+3][ra]=a.w;
        *(float4*)&Bs[rb][cb] = *(const float4*)&Bg[(size_t)(k0+rb)*N_ + cb];
        __syncthreads();
        #pragma unroll
        for (int kk = 0; kk < 16; kk++) {
            float4 a4 = *(float4*)&As[kk][ty<<2];
            float4 b4 = *(float4*)&Bs[kk][tx<<2];
            float ar[4]={a4.x,a4.y,a4.z,a4.w}, br[4]={b4.x,b4.y,b4.z,b4.w};
            #pragma unroll
            for (int i=0;i<4;i++)
                #pragma unroll
                for (int j=0;j<4;j++) acc[i][j] += ar[i]*br[j];
        }
        __syncthreads();
    }
    #pragma unroll
    for (int i = 0; i < 4; i++) {
        int m = mBase + (ty<<2) + i;
        float bi = bias[m];
        float4 o = make_float4(acc[i][0]+bi, acc[i][1]+bi, acc[i][2]+bi, acc[i][3]+bi);
        *(float4*)&Y[((size_t)b*OC + m)*N_ + nBase + (tx<<2)] = o;
    }
}

// ---------------- K3: attn[b,e,n,m] = scale * sum_c q[b,c,n]*k[b,e*C+c,m] ----
__global__ void qk_gemm()
{
    __shared__ float As[16][68];
    __shared__ float Bs[16][68];
    int z = blockIdx.z;                       // b*4+e
    int b = z >> 2;
    int nBase = blockIdx.y * 64;              // output row (n)
    int mBase = blockIdx.x * 64;              // output col (m)
    const float* Ag = g_q + (size_t)b*C_*N_ + nBase;      // [c][n]
    const float* Bg = g_k + (size_t)z*C_*N_ + mBase;      // [c][m]  (z*C = (b*4+e)*C)
    int tid = threadIdx.x, tx = tid & 15, ty = tid >> 4;
    int rb = tid >> 4, cb = (tid & 15) << 2;
    float acc[4][4] = {};
    for (int k0 = 0; k0 < C_; k0 += 16) {
        *(float4*)&As[rb][cb] = *(const float4*)&Ag[(size_t)(k0+rb)*N_ + cb];
        *(float4*)&Bs[rb][cb] = *(const float4*)&Bg[(size_t)(k0+rb)*N_ + cb];
        __syncthreads();
        #pragma unroll
        for (int kk = 0; kk < 16; kk++) {
            float4 a4 = *(float4*)&As[kk][ty<<2];
            float4 b4 = *(float4*)&Bs[kk][tx<<2];
            float ar[4]={a4.x,a4.y,a4.z,a4.w}, br[4]={b4.x,b4.y,b4.z,b4.w};
            #pragma unroll
            for (int i=0;i<4;i++)
                #pragma unroll
                for (int j=0;j<4;j++) acc[i][j] += ar[i]*br[j];
        }
        __syncthreads();
    }
    const float scale = 0.0625f;   // 256^-0.5
    #pragma unroll
    for (int i = 0; i < 4; i++) {
        int n = nBase + (ty<<2) + i;
        float4 o = make_float4(acc[i][0]*scale, acc[i][1]*scale, acc[i][2]*scale, acc[i][3]*scale);
        *(float4*)&g_attn[((size_t)z*N_ + n)*N_ + mBase + (tx<<2)] = o;
    }
}

// ------- K4: fused 3x3 conv(4->4) + BN + self-gated softmax over last dim ----
// one block = one output row n of one batch b (all 4 channels, all 1024 m)
__global__ void conv0_gate_kernel(const float* __restrict__ w0,
                                  const float* __restrict__ gma, const float* __restrict__ bta,
                                  const float* __restrict__ mu,  const float* __restrict__ var)
{
    __shared__ float rows[3][N_];
    __shared__ float wsm[144];
    __shared__ float red[256];
    int n = blockIdx.x, b = blockIdx.y, tid = threadIdx.x;
    if (tid < 144) wsm[tid] = w0[tid];
    float sc[4], sh[4];
    #pragma unroll
    for (int f = 0; f < 4; f++) {
        float inv = rsqrtf(var[f] + 1e-5f);
        sc[f] = gma[f] * inv; sh[f] = bta[f] - mu[f] * sc[f];
    }
    float acc[4][4] = {};
    for (int e = 0; e < 4; e++) {
        __syncthreads();
        #pragma unroll
        for (int r = 0; r < 3; r++) {
            int nn = n + r - 1;
            bool ok = (unsigned)nn < (unsigned)N_;
            const float* src = g_attn + (((size_t)(b*4 + e))*N_ + (ok ? nn : 0))*N_;
            for (int i = tid; i < N_; i += 256) rows[r][i] = ok ? src[i] : 0.f;
        }
        __syncthreads();
        #pragma unroll
        for (int t = 0; t < 9; t++) {
            int ky = t / 3, kx = t % 3;
            float w0r = wsm[(0*4+e)*9+t], w1r = wsm[(1*4+e)*9+t];
            float w2r = wsm[(2*4+e)*9+t], w3r = wsm[(3*4+e)*9+t];
            #pragma unroll
            for (int j = 0; j < 4; j++) {
                int m = tid + 256*j + kx - 1;
                float in = ((unsigned)m < (unsigned)N_) ? rows[ky][m] : 0.f;
                acc[0][j] += w0r*in; acc[1][j] += w1r*in;
                acc[2][j] += w2r*in; acc[3][j] += w3r*in;
            }
        }
    }
    #pragma unroll
    for (int f = 0; f < 4; f++)
        #pragma unroll
        for (int j = 0; j < 4; j++) acc[f][j] = acc[f][j]*sc[f] + sh[f];

    // per-channel softmax over the 1024 m positions, then gated write
    for (int f = 0; f < 4; f++) {
        float mx4 = fmaxf(fmaxf(acc[f][0], acc[f][1]), fmaxf(acc[f][2], acc[f][3]));
        __syncthreads();
        red[tid] = mx4; __syncthreads();
        for (int s = 128; s > 0; s >>= 1) { if (tid < s) red[tid] = fmaxf(red[tid], red[tid+s]); __syncthreads(); }
        float mx = red[0];
        float es[4]; float psum = 0.f;
        #pragma unroll
        for (int j = 0; j < 4; j++) { es[j] = expf(acc[f][j] - mx); psum += es[j]; }
        __syncthreads();
        red[tid] = psum; __syncthreads();
        for (int s = 128; s > 0; s >>= 1) { if (tid < s) red[tid] += red[tid+s]; __syncthreads(); }
        float inv = 1.f / red[0];
        float* dst = g_gated + (((size_t)(b*4 + f))*N_ + n)*N_;
        #pragma unroll
        for (int j = 0; j < 4; j++) dst[tid + 256*j] = acc[f][j] * es[j] * inv;
    }
}

// ---------------- K5: 3x3 conv(4->1) on gated -> final attn (second output) --
__global__ void attn1_kernel(const float* __restrict__ w1, float* __restrict__ dst)
{
    __shared__ float rows[3][N_];
    int n = blockIdx.x, b = blockIdx.y, tid = threadIdx.x;
    float acc[4] = {};
    for (int e = 0; e < 4; e++) {
        __syncthreads();
        #pragma unroll
        for (int r = 0; r < 3; r++) {
            int nn = n + r - 1;
            bool ok = (unsigned)nn < (unsigned)N_;
            const float* src = g_gated + (((size_t)(b*4 + e))*N_ + (ok ? nn : 0))*N_;
            for (int i = tid; i < N_; i += 256) rows[r][i] = ok ? src[i] : 0.f;
        }
        __syncthreads();
        #pragma unroll
        for (int t = 0; t < 9; t++) {
            float wv = w1[e*9 + t];
            int ky = t / 3, kx = t % 3;
            #pragma unroll
            for (int j = 0; j < 4; j++) {
                int m = tid + 256*j + kx - 1;
                float in = ((unsigned)m < (unsigned)N_) ? rows[ky][m] : 0.f;
                acc[j] += wv * in;
            }
        }
    }
    #pragma unroll
    for (int j = 0; j < 4; j++)
        dst[((size_t)b*N_ + n)*N_ + tid + 256*j] = acc[j];
}

// ---------------- K6: out0[b,c,n] = sum_m v[b,c,m]*attnF[b,n,m]  (NT GEMM) ---
__global__ void av_gemm(const float* __restrict__ attnF)
{
    __shared__ float As[16][68];
    __shared__ float Bs[16][68];
    int b = blockIdx.z;
    int mBase = blockIdx.y * 64;   // c
    int nBase = blockIdx.x * 64;   // n
    const float* Ag = g_v  + ((size_t)b*C_ + mBase)*N_;   // [c][m], K-minor
    const float* Bg = attnF + (size_t)b*NN_ + (size_t)nBase*N_; // [n][m], K-minor
    int tid = threadIdx.x, tx = tid & 15, ty = tid >> 4;
    int r = tid >> 2, c4 = (tid & 3) << 2;
    float acc[4][4] = {};
    for (int k0 = 0; k0 < N_; k0 += 16) {
        float4 a = *(const float4*)&Ag[(size_t)r*N_ + k0 + c4];
        As[c4+0][r]=a.x; As[c4+1][r]=a.y; As[c4+2][r]=a.z; As[c4+3][r]=a.w;
        float4 bq = *(const float4*)&Bg[(size_t)r*N_ + k0 + c4];
        Bs[c4+0][r]=bq.x; Bs[c4+1][r]=bq.y; Bs[c4+2][r]=bq.z; Bs[c4+3][r]=bq.w;
        __syncthreads();
        #pragma unroll
        for (int kk = 0; kk < 16; kk++) {
            float4 a4 = *(float4*)&As[kk][ty<<2];
            float4 b4 = *(float4*)&Bs[kk][tx<<2];
            float ar[4]={a4.x,a4.y,a4.z,a4.w}, br[4]={b4.x,b4.y,b4.z,b4.w};
            #pragma unroll
            for (int i=0;i<4;i++)
                #pragma unroll
                for (int j=0;j<4;j++) acc[i][j] += ar[i]*br[j];
        }
        __syncthreads();
    }
    #pragma unroll
    for (int i = 0; i < 4; i++) {
        int c = mBase + (ty<<2) + i;
        float4 o = make_float4(acc[i][0], acc[i][1], acc[i][2], acc[i][3]);
        *(float4*)&g_out0[((size_t)b*C_ + c)*N_ + nBase + (tx<<2)] = o;
    }
}

// ---------------- K7: proj 3x3 conv (256->256, no bias) -> first output ------
__global__ void proj_kernel(const float* __restrict__ pw, float* __restrict__ dst)
{
    __shared__ float inT[8][34*34];
    __shared__ float wT[4][8][9];
    int ocg = blockIdx.x;          // 0..63 (4 oc each)
    int b   = blockIdx.y;
    int tid = threadIdx.x;
    int base34[4];
    #pragma unroll
    for (int i = 0; i < 4; i++) {
        int sp = tid + 256*i; int h = sp >> 5, w = sp & 31;
        base34[i] = h*34 + w;      // tile index of (h-1,w-1) shifted by halo
    }
    float acc[4][4] = {};
    for (int cc = 0; cc < 32; cc++) {
        __syncthreads();
        for (int idx = tid; idx < 8*1156; idx += 256) {
            int ic = idx / 1156, rem = idx % 1156;
            int hh = rem / 34 - 1, ww = rem % 34 - 1;
            float v = 0.f;
            if ((unsigned)hh < 32u && (unsigned)ww < 32u)
                v = g_out0[((size_t)b*C_ + cc*8 + ic)*N_ + hh*32 + ww];
            inT[ic][rem] = v;
        }
        for (int idx = tid; idx < 288; idx += 256) {
            int oc = idx / 72, r2 = idx % 72, ic = r2 / 9, t = r2 % 9;
            wT[oc][ic][t] = pw[((size_t)(ocg*4 + oc)*C_ + cc*8 + ic)*9 + t];
        }
        __syncthreads();
        #pragma unroll
        for (int ic = 0; ic < 8; ic++) {
            #pragma unroll
            for (int t = 0; t < 9; t++) {
                int off = (t/3)*34 + (t%3);
                float w0 = wT[0][ic][t], w1 = wT[1][ic][t];
                float w2 = wT[2][ic][t], w3 = wT[3][ic][t];
                #pragma unroll
                for (int i = 0; i < 4; i++) {
                    float in = inT[ic][base34[i] + off];
                    acc[0][i] += w0*in; acc[1][i] += w1*in;
                    acc[2][i] += w2*in; acc[3][i] += w3*in;
                }
            }
        }
    }
    #pragma unroll
    for (int oc = 0; oc < 4; oc++)
        #pragma unroll
        for (int i = 0; i < 4; i++)
            dst[((size_t)b*C_ + ocg*4 + oc)*N_ + tid + 256*i] = acc[oc][i];
}

// ---------------------------------------------------------------------------
extern "C" void kernel_launch(void* const* d_in, const int* in_sizes, int n_in,
                              void* d_out, int out_size)
{
    const float* x       = (const float*)d_in[0];
    const float* qa_dw_w = (const float*)d_in[1];
    const float* qa_dw_b = (const float*)d_in[2];
    const float* qa_pw_w = (const float*)d_in[3];
    const float* qa_pw_b = (const float*)d_in[4];
    const float* ka_dw_w = (const float*)d_in[5];
    const float* ka_dw_b = (const float*)d_in[6];
    const float* ka_pw_w = (const float*)d_in[7];
    const float* ka_pw_b = (const float*)d_in[8];
    const float* va_dw_w = (const float*)d_in[9];
    const float* va_dw_b = (const float*)d_in[10];
    const float* va_pw_w = (const float*)d_in[11];
    const float* va_pw_b = (const float*)d_in[12];
    const float* attn0_w = (const float*)d_in[13];
    const float* bn_g    = (const float*)d_in[14];
    const float* bn_b    = (const float*)d_in[15];
    const float* bn_m    = (const float*)d_in[16];
    const float* bn_v    = (const float*)d_in[17];
    const float* attn1_w = (const float*)d_in[18];
    const float* proj_w  = (const float*)d_in[19];

    float* out_main = (float*)d_out;                 // [8,256,32,32]
    float* out_attn = out_main + (size_t)B_*C_*N_;   // [8,1,1024,1024]

    void *p_dwq, *p_dwk, *p_dwv, *p_q, *p_k, *p_v;
    cudaGetSymbolAddress(&p_dwq, g_dwq);
    cudaGetSymbolAddress(&p_dwk, g_dwk);
    cudaGetSymbolAddress(&p_dwv, g_dwv);
    cudaGetSymbolAddress(&p_q,   g_q);
    cudaGetSymbolAddress(&p_k,   g_k);
    cudaGetSymbolAddress(&p_v,   g_v);

    // K1: fused depthwise for q/k/v branches
    dw3_kernel<<<B_*C_, 256>>>(x, qa_dw_w, qa_dw_b, ka_dw_w, ka_dw_b, va_dw_w, va_dw_b);

    // K2: pointwise GEMMs (+bias)
    pw_gemm<<<dim3(16, 4, B_), 256>>>(qa_pw_w, qa_pw_b, (const float*)p_dwq, (float*)p_q, 256);
    pw_gemm<<<dim3(16,16, B_), 256>>>(ka_pw_w, ka_pw_b, (const float*)p_dwk, (float*)p_k, 1024);
    pw_gemm<<<dim3(16, 4, B_), 256>>>(va_pw_w, va_pw_b, (const float*)p_dwv, (float*)p_v, 256);

    // K3: q^T k  -> attn [B,4,N,N], scaled
    qk_gemm<<<dim3(16, 16, B_*EXP_), 256>>>();

    // K4: conv0 + BN + self-gated softmax (fused, row-wise)
    conv0_gate_kernel<<<dim3(N_, B_), 256>>>(attn0_w, bn_g, bn_b, bn_m, bn_v);

    // K5: conv attn1 (4->1) -> second output
    attn1_kernel<<<dim3(N_, B_), 256>>>(attn1_w, out_attn);

    // K6: attn @ v^T -> out0
    av_gemm<<<dim3(16, 4, B_), 256>>>(out_attn);

    // K7: proj 3x3 conv -> first output
    proj_kernel<<<dim3(64, B_), 256>>>(proj_w, out_main);
}